// round 7
// baseline (speedup 1.0000x reference)
#include <cuda_runtime.h>
#include <cuda_bf16.h>
#include <cstdint>
#include <math.h>

#define EPSV 1e-5f
#define BATCH 4096
#define HDIM 4096
#define DIN 1024
#define NOUT 2000
#define NOUT_PAD 2048

// ---------------- scratch (device globals: allocation-free) ----------------
__device__ __align__(16) __nv_bfloat16 g_A[BATCH * HDIM];   // quantized activations (int-valued bf16)
__device__ __align__(16) __nv_bfloat16 g_W[HDIM * HDIM];    // ternary weights (bf16), reused per layer
__device__ float  g_C[BATCH * HDIM];                        // raw GEMM output (integer-valued fp32)
__device__ float  g_rs[BATCH];                              // per-row activation dequant (1/scale)
__device__ float  g_wpart[4][2048];                         // per-block partial |W| sums
__device__ double g_wsum[4];                                // total |W| sums

// ================= helpers =================
__device__ __forceinline__ uint32_t smem_u32(const void* p) {
    uint32_t a;
    asm("{ .reg .u64 t; cvta.to.shared.u64 t, %1; cvt.u32.u64 %0, t; }" : "=r"(a) : "l"(p));
    return a;
}
__device__ __forceinline__ void cp16(uint32_t dst, const void* src) {
    asm volatile("cp.async.cg.shared.global [%0], [%1], 16;\n" :: "r"(dst), "l"(src));
}
#define CP_COMMIT() asm volatile("cp.async.commit_group;\n" ::: "memory")
#define CP_WAIT2()  asm volatile("cp.async.wait_group 2;\n" ::: "memory")

__device__ __forceinline__ void ldsm_x4(uint32_t& r0, uint32_t& r1, uint32_t& r2, uint32_t& r3,
                                        uint32_t addr) {
    asm volatile("ldmatrix.sync.aligned.m8n8.x4.shared.b16 {%0,%1,%2,%3}, [%4];"
                 : "=r"(r0), "=r"(r1), "=r"(r2), "=r"(r3) : "r"(addr));
}

// ---------------- reductions ----------------
__device__ __forceinline__ float blockReduceSum(float val) {
    __shared__ float sm[32];
    int lane = threadIdx.x & 31, wid = threadIdx.x >> 5;
#pragma unroll
    for (int o = 16; o; o >>= 1) val += __shfl_xor_sync(0xffffffffu, val, o);
    if (lane == 0) sm[wid] = val;
    __syncthreads();
    if (wid == 0) {
        val = (lane < (blockDim.x >> 5)) ? sm[lane] : 0.f;
#pragma unroll
        for (int o = 16; o; o >>= 1) val += __shfl_xor_sync(0xffffffffu, val, o);
        if (lane == 0) sm[0] = val;
    }
    __syncthreads();
    float r = sm[0];
    __syncthreads();
    return r;
}

__device__ __forceinline__ float blockReduceMax(float val) {
    __shared__ float sm[32];
    int lane = threadIdx.x & 31, wid = threadIdx.x >> 5;
#pragma unroll
    for (int o = 16; o; o >>= 1) val = fmaxf(val, __shfl_xor_sync(0xffffffffu, val, o));
    if (lane == 0) sm[wid] = val;
    __syncthreads();
    if (wid == 0) {
        val = (lane < (blockDim.x >> 5)) ? sm[lane] : 0.f;
#pragma unroll
        for (int o = 16; o; o >>= 1) val = fmaxf(val, __shfl_xor_sync(0xffffffffu, val, o));
        if (lane == 0) sm[0] = val;
    }
    __syncthreads();
    float r = sm[0];
    __syncthreads();
    return r;
}

// ---------------- weight abs-mean pass 1 (fp32, deterministic fixed-order) ----------------
__global__ void wsum_kernel(const float* __restrict__ W, int n, int idx) {
    const float4* W4 = (const float4*)W;
    int n4 = n >> 2;
    float s = 0.0f;
    for (int i = blockIdx.x * blockDim.x + threadIdx.x; i < n4; i += gridDim.x * blockDim.x) {
        float4 v = W4[i];
        s += fabsf(v.x) + fabsf(v.y) + fabsf(v.z) + fabsf(v.w);
    }
    __shared__ float sm[256];
    sm[threadIdx.x] = s;
    __syncthreads();
    for (int o = 128; o; o >>= 1) {
        if (threadIdx.x < o) sm[threadIdx.x] += sm[threadIdx.x + o];
        __syncthreads();
    }
    if (threadIdx.x == 0) g_wpart[idx][blockIdx.x] = sm[0];
}

__global__ void wreduce_kernel() {
    int idx = blockIdx.x;
    double s = 0.0;
    for (int i = threadIdx.x; i < 2048; i += 256) s += (double)g_wpart[idx][i];
    __shared__ double sm[256];
    sm[threadIdx.x] = s;
    __syncthreads();
    for (int o = 128; o; o >>= 1) {
        if (threadIdx.x < o) sm[threadIdx.x] += sm[threadIdx.x + o];
        __syncthreads();
    }
    if (threadIdx.x == 0) g_wsum[idx] = sm[0];
}

// ---------------- ternarize weights into bf16 scratch (8 elems/thread) ----------------
__global__ void tern_kernel(const float* __restrict__ W, int rows, int cols,
                            int rows_pad, int idx, double count) {
    float mean = (float)(g_wsum[idx] / count);
    float scale = 1.0f / fmaxf(mean, EPSV);
    int n8 = (rows_pad * cols) >> 3;
    for (int i8 = blockIdx.x * blockDim.x + threadIdx.x; i8 < n8; i8 += gridDim.x * blockDim.x) {
        int r = (i8 << 3) / cols;
        __nv_bfloat16 o[8];
        if (r < rows) {
            const float4* p = (const float4*)(W + ((size_t)i8 << 3));
            float4 a = p[0], b = p[1];
            float v[8] = {a.x, a.y, a.z, a.w, b.x, b.y, b.z, b.w};
#pragma unroll
            for (int k = 0; k < 8; k++) {
                float t = rintf(v[k] * scale);
                o[k] = __float2bfloat16(fminf(fmaxf(t, -1.0f), 1.0f));
            }
        } else {
#pragma unroll
            for (int k = 0; k < 8; k++) o[k] = __float2bfloat16(0.0f);
        }
        *(uint4*)(g_W + ((size_t)i8 << 3)) = *(const uint4*)o;
    }
}

// ---------------- quantize input x ----------------
__global__ void actquant_x(const float* __restrict__ x) {
    int row = blockIdx.x;
    const float* xr = x + (size_t)row * DIN;
    float m = 0.0f;
    for (int j = threadIdx.x; j < DIN; j += 256) m = fmaxf(m, fabsf(xr[j]));
    m = blockReduceMax(m);
    float scale = 127.0f / fmaxf(m, EPSV);
    for (int j = threadIdx.x; j < DIN; j += 256) {
        float q = rintf(xr[j] * scale);
        q = fminf(fmaxf(q, -128.0f), 127.0f);
        g_A[(size_t)row * DIN + j] = __float2bfloat16(q);
    }
    if (threadIdx.x == 0) g_rs[row] = 1.0f / scale;
}

// ================ bf16 HMMA GEMM: C[M,N] = g_A[M,K] @ g_W[N,K]^T ================
// 128x128 CTA tile, 4 warps (2x2), warp tile 64x64, K chunk 64,
// 3-stage cp.async ring, ldmatrix fragment loads. 144B rows: LDSM conflict-free.
#define SROWE 72
#define STAGE_B (128 * SROWE * 2)          // bytes per matrix per stage (18432)
#define GEMM_SMEM (6 * STAGE_B)            // 3 stages x (A,B) = 110592

__global__ __launch_bounds__(128, 2) void gemm_bf16(int K, int ldc) {
    extern __shared__ __align__(16) char smem[];
    const uint32_t sbase = smem_u32(smem);
    const int tid = threadIdx.x;
    const int lane = tid & 31;
    const int wid = tid >> 5;
    const int wm = (wid >> 1) * 64;   // warp M offset (0/64)
    const int wn = (wid & 1) * 64;    // warp N offset (0/64)
    const int bm = blockIdx.y * 128;
    const int bn = blockIdx.x * 128;
    const int NC = K >> 6;            // 64-wide K chunks

    const __nv_bfloat16* Ag = g_A + (size_t)bm * K;
    const __nv_bfloat16* Bg = g_W + (size_t)bn * K;

    // each of 128 threads loads one 128B row-chunk (8 x cp16) per matrix per chunk
    auto load_chunk = [&](int c, int buf) {
        int k0 = c << 6;
        uint32_t da = sbase + buf * 2 * STAGE_B;
        uint32_t db = da + STAGE_B;
        const __nv_bfloat16* arow = Ag + (size_t)tid * K + k0;
        const __nv_bfloat16* brow = Bg + (size_t)tid * K + k0;
        uint32_t off = tid * (SROWE * 2);
#pragma unroll
        for (int j = 0; j < 8; j++) {
            cp16(da + off + j * 16, arow + j * 8);
            cp16(db + off + j * 16, brow + j * 8);
        }
    };

    float acc[4][8][4];
#pragma unroll
    for (int i = 0; i < 4; i++)
#pragma unroll
        for (int j = 0; j < 8; j++)
#pragma unroll
            for (int k = 0; k < 4; k++) acc[i][j][k] = 0.0f;

    // prologue: chunks 0 and 1 in flight
    load_chunk(0, 0);
    CP_COMMIT();
    if (NC > 1) load_chunk(1, 1);
    CP_COMMIT();

    // ldmatrix lane addressing
    const int a_row_off = (lane & 7) + ((lane >> 3) & 1) * 8;
    const int a_col_off = (lane >> 4) * 8;
    const int b_row_off = (lane & 7) + ((lane >> 4) & 1) * 8;
    const int b_col_off = ((lane >> 3) & 1) * 8;

    int buf = 0;          // = c % 3
    int buf2 = 2;         // = (c+2) % 3
    for (int c = 0; c < NC; c++) {
        if (c + 2 < NC) load_chunk(c + 2, buf2);
        CP_COMMIT();
        CP_WAIT2();       // >= chunk c complete
        __syncthreads();

        uint32_t Abase = sbase + buf * 2 * STAGE_B;
        uint32_t Bbase = Abase + STAGE_B;

#pragma unroll
        for (int kk = 0; kk < 64; kk += 16) {
            uint32_t af[4][4];
#pragma unroll
            for (int mi = 0; mi < 4; mi++) {
                uint32_t addr = Abase + (uint32_t)((wm + mi * 16 + a_row_off) * (SROWE * 2)
                                                   + (kk + a_col_off) * 2);
                ldsm_x4(af[mi][0], af[mi][1], af[mi][2], af[mi][3], addr);
            }
            uint32_t bfr[8][2];
#pragma unroll
            for (int nip = 0; nip < 4; nip++) {
                uint32_t addr = Bbase + (uint32_t)((wn + nip * 16 + b_row_off) * (SROWE * 2)
                                                   + (kk + b_col_off) * 2);
                ldsm_x4(bfr[nip * 2][0], bfr[nip * 2][1],
                        bfr[nip * 2 + 1][0], bfr[nip * 2 + 1][1], addr);
            }
#pragma unroll
            for (int mi = 0; mi < 4; mi++)
#pragma unroll
                for (int ni = 0; ni < 8; ni++)
                    asm volatile(
                        "mma.sync.aligned.m16n8k16.row.col.f32.bf16.bf16.f32 "
                        "{%0,%1,%2,%3}, {%4,%5,%6,%7}, {%8,%9}, {%0,%1,%2,%3};\n"
                        : "+f"(acc[mi][ni][0]), "+f"(acc[mi][ni][1]),
                          "+f"(acc[mi][ni][2]), "+f"(acc[mi][ni][3])
                        : "r"(af[mi][0]), "r"(af[mi][1]), "r"(af[mi][2]), "r"(af[mi][3]),
                          "r"(bfr[ni][0]), "r"(bfr[ni][1]));
        }
        __syncthreads();
        buf = (buf == 2) ? 0 : buf + 1;
        buf2 = (buf2 == 2) ? 0 : buf2 + 1;
    }

#pragma unroll
    for (int mi = 0; mi < 4; mi++) {
#pragma unroll
        for (int ni = 0; ni < 8; ni++) {
            int r = bm + wm + mi * 16 + (lane >> 2);
            int cc = bn + wn + ni * 8 + (lane & 3) * 2;
            *(float2*)&g_C[(size_t)r * ldc + cc] = make_float2(acc[mi][ni][0], acc[mi][ni][1]);
            *(float2*)&g_C[(size_t)(r + 8) * ldc + cc] = make_float2(acc[mi][ni][2], acc[mi][ni][3]);
        }
    }
}

// ---------------- fused scale + LayerNorm + SiLU + re-quantize ----------------
__global__ void ln_silu_quant(const float* __restrict__ gamma, const float* __restrict__ beta,
                              int widx, double count) {
    int row = blockIdx.x;
    float wmean = fmaxf((float)(g_wsum[widx] / count), EPSV);
    float f = g_rs[row] * wmean;
    const float* cr = g_C + (size_t)row * HDIM;

    float v[16];
    float s = 0.0f;
#pragma unroll
    for (int i = 0; i < 16; i++) {
        v[i] = cr[threadIdx.x + i * 256] * f;
        s += v[i];
    }
    s = blockReduceSum(s);
    float mu = s * (1.0f / HDIM);

    float s2 = 0.0f;
#pragma unroll
    for (int i = 0; i < 16; i++) {
        float d = v[i] - mu;
        s2 += d * d;
    }
    s2 = blockReduceSum(s2);
    float inv_std = rsqrtf(s2 * (1.0f / HDIM) + EPSV);

    float y[16];
    float mx = 0.0f;
#pragma unroll
    for (int i = 0; i < 16; i++) {
        int j = threadIdx.x + i * 256;
        float t = (v[i] - mu) * inv_std * gamma[j] + beta[j];
        t = t / (1.0f + __expf(-t));  // silu
        y[i] = t;
        mx = fmaxf(mx, fabsf(t));
    }
    mx = blockReduceMax(mx);
    float scale = 127.0f / fmaxf(mx, EPSV);
#pragma unroll
    for (int i = 0; i < 16; i++) {
        int j = threadIdx.x + i * 256;
        float q = rintf(y[i] * scale);
        q = fminf(fmaxf(q, -128.0f), 127.0f);
        g_A[(size_t)row * HDIM + j] = __float2bfloat16(q);
    }
    if (threadIdx.x == 0) g_rs[row] = 1.0f / scale;
}

// ---------------- final sigmoid split ----------------
__global__ void final_kernel(float* __restrict__ out, double count) {
    int idx = blockIdx.x * blockDim.x + threadIdx.x;
    if (idx >= BATCH * 1000) return;
    int row = idx / 1000;
    int j = idx - row * 1000;
    float wmean = fmaxf((float)(g_wsum[3] / count), EPSV);
    float f = g_rs[row] * wmean;
    float l1 = g_C[(size_t)row * NOUT_PAD + j] * f;
    float l2 = g_C[(size_t)row * NOUT_PAD + 1000 + j] * f;
    float mz = 999.0f / (1.0f + __expf(-l1)) + 1.0f;
    float it = 100.0f / (1.0f + __expf(-l2));
    out[(size_t)row * 1000 + j] = mz;
    out[(size_t)BATCH * 1000 + (size_t)row * 1000 + j] = it;
}

// ---------------- launch ----------------
extern "C" void kernel_launch(void* const* d_in, const int* in_sizes, int n_in,
                              void* d_out, int out_size) {
    const float* x  = (const float*)d_in[0];
    const float* W0 = (const float*)d_in[1];
    const float* W1 = (const float*)d_in[2];
    const float* W2 = (const float*)d_in[3];
    const float* W3 = (const float*)d_in[4];
    const float* g0 = (const float*)d_in[5];
    const float* b0 = (const float*)d_in[6];
    const float* g1 = (const float*)d_in[7];
    const float* b1 = (const float*)d_in[8];
    const float* g2 = (const float*)d_in[9];
    const float* b2 = (const float*)d_in[10];
    float* out = (float*)d_out;

    cudaFuncSetAttribute(gemm_bf16, cudaFuncAttributeMaxDynamicSharedMemorySize, GEMM_SMEM);

    const double c0 = (double)HDIM * DIN;
    const double c1 = (double)HDIM * HDIM;
    const double c3 = (double)NOUT * HDIM;

    wsum_kernel<<<2048, 256>>>(W0, HDIM * DIN, 0);
    wsum_kernel<<<2048, 256>>>(W1, HDIM * HDIM, 1);
    wsum_kernel<<<2048, 256>>>(W2, HDIM * HDIM, 2);
    wsum_kernel<<<2048, 256>>>(W3, NOUT * HDIM, 3);
    wreduce_kernel<<<4, 256>>>();

    actquant_x<<<BATCH, 256>>>(x);

    // Layer 0: K=1024
    tern_kernel<<<2048, 256>>>(W0, HDIM, DIN, HDIM, 0, c0);
    gemm_bf16<<<dim3(HDIM / 128, BATCH / 128), 128, GEMM_SMEM>>>(DIN, HDIM);
    ln_silu_quant<<<BATCH, 256>>>(g0, b0, 0, c0);

    // Layer 1
    tern_kernel<<<2048, 256>>>(W1, HDIM, HDIM, HDIM, 1, c1);
    gemm_bf16<<<dim3(HDIM / 128, BATCH / 128), 128, GEMM_SMEM>>>(HDIM, HDIM);
    ln_silu_quant<<<BATCH, 256>>>(g1, b1, 1, c1);

    // Layer 2
    tern_kernel<<<2048, 256>>>(W2, HDIM, HDIM, HDIM, 2, c1);
    gemm_bf16<<<dim3(HDIM / 128, BATCH / 128), 128, GEMM_SMEM>>>(HDIM, HDIM);
    ln_silu_quant<<<BATCH, 256>>>(g2, b2, 2, c1);

    // Layer 3: output head, N padded 2000 -> 2048 with zero rows
    tern_kernel<<<2048, 256>>>(W3, NOUT, HDIM, NOUT_PAD, 3, c3);
    gemm_bf16<<<dim3(NOUT_PAD / 128, BATCH / 128), 128, GEMM_SMEM>>>(HDIM, NOUT_PAD);
    final_kernel<<<(BATCH * 1000 + 255) / 256, 256>>>(out, c3);
}

// round 8
// speedup vs baseline: 1.2604x; 1.2604x over previous
#include <cuda_runtime.h>
#include <cuda_bf16.h>
#include <cstdint>
#include <math.h>

#define EPSV 1e-5f
#define BATCH 4096
#define HDIM 4096
#define DIN 1024
#define NOUT 2000
#define NOUT_PAD 2048

// ---------------- scratch (device globals: allocation-free) ----------------
__device__ __align__(16) __nv_bfloat16 g_A[BATCH * HDIM];   // quantized activations (int-valued bf16)
__device__ __align__(16) __nv_bfloat16 g_W[HDIM * HDIM];    // ternary weights (bf16), reused per layer
__device__ float  g_C[BATCH * HDIM];                        // raw GEMM output (integer-valued fp32)
__device__ float  g_rs[BATCH];                              // per-row activation dequant (1/scale)
__device__ float  g_wpart[4][2048];                         // per-block partial |W| sums
__device__ double g_wsum[4];                                // total |W| sums

// ================= helpers =================
__device__ __forceinline__ uint32_t smem_u32(const void* p) {
    uint32_t a;
    asm("{ .reg .u64 t; cvta.to.shared.u64 t, %1; cvt.u32.u64 %0, t; }" : "=r"(a) : "l"(p));
    return a;
}
__device__ __forceinline__ void cp16(uint32_t dst, const void* src) {
    asm volatile("cp.async.cg.shared.global [%0], [%1], 16;\n" :: "r"(dst), "l"(src));
}
#define CP_COMMIT() asm volatile("cp.async.commit_group;\n" ::: "memory")
#define CP_WAIT1()  asm volatile("cp.async.wait_group 1;\n" ::: "memory")

__device__ __forceinline__ void ldsm_x4(uint32_t& r0, uint32_t& r1, uint32_t& r2, uint32_t& r3,
                                        uint32_t addr) {
    asm volatile("ldmatrix.sync.aligned.m8n8.x4.shared.b16 {%0,%1,%2,%3}, [%4];"
                 : "=r"(r0), "=r"(r1), "=r"(r2), "=r"(r3) : "r"(addr));
}

// ---------------- reductions ----------------
__device__ __forceinline__ float blockReduceSum(float val) {
    __shared__ float sm[32];
    int lane = threadIdx.x & 31, wid = threadIdx.x >> 5;
#pragma unroll
    for (int o = 16; o; o >>= 1) val += __shfl_xor_sync(0xffffffffu, val, o);
    if (lane == 0) sm[wid] = val;
    __syncthreads();
    if (wid == 0) {
        val = (lane < (blockDim.x >> 5)) ? sm[lane] : 0.f;
#pragma unroll
        for (int o = 16; o; o >>= 1) val += __shfl_xor_sync(0xffffffffu, val, o);
        if (lane == 0) sm[0] = val;
    }
    __syncthreads();
    float r = sm[0];
    __syncthreads();
    return r;
}

__device__ __forceinline__ float blockReduceMax(float val) {
    __shared__ float sm[32];
    int lane = threadIdx.x & 31, wid = threadIdx.x >> 5;
#pragma unroll
    for (int o = 16; o; o >>= 1) val = fmaxf(val, __shfl_xor_sync(0xffffffffu, val, o));
    if (lane == 0) sm[wid] = val;
    __syncthreads();
    if (wid == 0) {
        val = (lane < (blockDim.x >> 5)) ? sm[lane] : 0.f;
#pragma unroll
        for (int o = 16; o; o >>= 1) val = fmaxf(val, __shfl_xor_sync(0xffffffffu, val, o));
        if (lane == 0) sm[0] = val;
    }
    __syncthreads();
    float r = sm[0];
    __syncthreads();
    return r;
}

// ---------------- weight abs-mean pass 1 (fp32, deterministic fixed-order) ----------------
__global__ void wsum_kernel(const float* __restrict__ W, int n, int idx) {
    const float4* W4 = (const float4*)W;
    int n4 = n >> 2;
    float s = 0.0f;
    for (int i = blockIdx.x * blockDim.x + threadIdx.x; i < n4; i += gridDim.x * blockDim.x) {
        float4 v = W4[i];
        s += fabsf(v.x) + fabsf(v.y) + fabsf(v.z) + fabsf(v.w);
    }
    __shared__ float sm[256];
    sm[threadIdx.x] = s;
    __syncthreads();
    for (int o = 128; o; o >>= 1) {
        if (threadIdx.x < o) sm[threadIdx.x] += sm[threadIdx.x + o];
        __syncthreads();
    }
    if (threadIdx.x == 0) g_wpart[idx][blockIdx.x] = sm[0];
}

__global__ void wreduce_kernel() {
    int idx = blockIdx.x;
    double s = 0.0;
    for (int i = threadIdx.x; i < 2048; i += 256) s += (double)g_wpart[idx][i];
    __shared__ double sm[256];
    sm[threadIdx.x] = s;
    __syncthreads();
    for (int o = 128; o; o >>= 1) {
        if (threadIdx.x < o) sm[threadIdx.x] += sm[threadIdx.x + o];
        __syncthreads();
    }
    if (threadIdx.x == 0) g_wsum[idx] = sm[0];
}

// ---------------- ternarize weights into bf16 scratch (8 elems/thread) ----------------
__global__ void tern_kernel(const float* __restrict__ W, int rows, int cols,
                            int rows_pad, int idx, double count) {
    float mean = (float)(g_wsum[idx] / count);
    float scale = 1.0f / fmaxf(mean, EPSV);
    int n8 = (rows_pad * cols) >> 3;
    for (int i8 = blockIdx.x * blockDim.x + threadIdx.x; i8 < n8; i8 += gridDim.x * blockDim.x) {
        int r = (i8 << 3) / cols;
        __nv_bfloat16 o[8];
        if (r < rows) {
            const float4* p = (const float4*)(W + ((size_t)i8 << 3));
            float4 a = p[0], b = p[1];
            float v[8] = {a.x, a.y, a.z, a.w, b.x, b.y, b.z, b.w};
#pragma unroll
            for (int k = 0; k < 8; k++) {
                float t = rintf(v[k] * scale);
                o[k] = __float2bfloat16(fminf(fmaxf(t, -1.0f), 1.0f));
            }
        } else {
#pragma unroll
            for (int k = 0; k < 8; k++) o[k] = __float2bfloat16(0.0f);
        }
        *(uint4*)(g_W + ((size_t)i8 << 3)) = *(const uint4*)o;
    }
}

// ---------------- quantize input x ----------------
__global__ void actquant_x(const float* __restrict__ x) {
    int row = blockIdx.x;
    const float* xr = x + (size_t)row * DIN;
    float m = 0.0f;
    for (int j = threadIdx.x; j < DIN; j += 256) m = fmaxf(m, fabsf(xr[j]));
    m = blockReduceMax(m);
    float scale = 127.0f / fmaxf(m, EPSV);
    for (int j = threadIdx.x; j < DIN; j += 256) {
        float q = rintf(xr[j] * scale);
        q = fminf(fmaxf(q, -128.0f), 127.0f);
        g_A[(size_t)row * DIN + j] = __float2bfloat16(q);
    }
    if (threadIdx.x == 0) g_rs[row] = 1.0f / scale;
}

// ================ bf16 HMMA GEMM: C[M,N] = g_A[M,K] @ g_W[N,K]^T ================
// 128x128 CTA tile, 8 warps (2x4), warp tile 64x32, K chunk 64,
// 3-stage cp.async ring with ONE barrier per chunk, ldmatrix fragment loads.
// 144B smem rows: LDSM conflict-free.
#define SROWE 72
#define STAGE_B (128 * SROWE * 2)          // bytes per matrix per stage (18432)
#define GEMM_SMEM (6 * STAGE_B)            // 3 stages x (A,B) = 110592

__global__ __launch_bounds__(256, 2) void gemm_bf16(int K, int ldc) {
    extern __shared__ __align__(16) char smem[];
    const uint32_t sbase = smem_u32(smem);
    const int tid = threadIdx.x;
    const int lane = tid & 31;
    const int wid = tid >> 5;
    const int wm = (wid >> 2) * 64;   // warp M offset (0/64)
    const int wn = (wid & 3) * 32;    // warp N offset (0..96)
    const int bm = blockIdx.y * 128;
    const int bn = blockIdx.x * 128;
    const int NC = K >> 6;            // 64-wide K chunks

    const __nv_bfloat16* Ag = g_A + (size_t)bm * K;
    const __nv_bfloat16* Bg = g_W + (size_t)bn * K;

    const int lrow = tid >> 1;            // 0..127 row
    const int lj = (tid & 1) * 4;         // 16B chunks {0..3} or {4..7}

    auto load_chunk = [&](int c, int buf) {
        int k0 = c << 6;
        uint32_t da = sbase + buf * 2 * STAGE_B;
        uint32_t db = da + STAGE_B;
        const __nv_bfloat16* arow = Ag + (size_t)lrow * K + k0;
        const __nv_bfloat16* brow = Bg + (size_t)lrow * K + k0;
        uint32_t off = lrow * (SROWE * 2) + lj * 16;
#pragma unroll
        for (int j = 0; j < 4; j++) {
            cp16(da + off + j * 16, arow + (lj + j) * 8);
            cp16(db + off + j * 16, brow + (lj + j) * 8);
        }
    };

    float acc[4][4][4];
#pragma unroll
    for (int i = 0; i < 4; i++)
#pragma unroll
        for (int j = 0; j < 4; j++)
#pragma unroll
            for (int k = 0; k < 4; k++) acc[i][j][k] = 0.0f;

    // prologue: chunks 0 and 1 in flight
    load_chunk(0, 0);
    CP_COMMIT();
    if (NC > 1) load_chunk(1, 1);
    CP_COMMIT();

    // ldmatrix lane addressing
    const int a_row_off = (lane & 7) + ((lane >> 3) & 1) * 8;
    const int a_col_off = (lane >> 4) * 8;
    const int b_row_off = (lane & 7) + ((lane >> 4) & 1) * 8;
    const int b_col_off = ((lane >> 3) & 1) * 8;

    int buf = 0;          // = c % 3
    int buf2 = 2;         // = (c+2) % 3
    for (int c = 0; c < NC; c++) {
        CP_WAIT1();       // chunk c resident (<=1 newer group outstanding)
        __syncthreads();  // single barrier: prior reads of buf2 done across CTA

        if (c + 2 < NC) load_chunk(c + 2, buf2);
        CP_COMMIT();      // keep group count in lockstep even when no load

        uint32_t Abase = sbase + buf * 2 * STAGE_B;
        uint32_t Bbase = Abase + STAGE_B;

#pragma unroll
        for (int kk = 0; kk < 64; kk += 16) {
            uint32_t af[4][4];
#pragma unroll
            for (int mi = 0; mi < 4; mi++) {
                uint32_t addr = Abase + (uint32_t)((wm + mi * 16 + a_row_off) * (SROWE * 2)
                                                   + (kk + a_col_off) * 2);
                ldsm_x4(af[mi][0], af[mi][1], af[mi][2], af[mi][3], addr);
            }
            uint32_t bfr[4][2];
#pragma unroll
            for (int nip = 0; nip < 2; nip++) {
                uint32_t addr = Bbase + (uint32_t)((wn + nip * 16 + b_row_off) * (SROWE * 2)
                                                   + (kk + b_col_off) * 2);
                ldsm_x4(bfr[nip * 2][0], bfr[nip * 2][1],
                        bfr[nip * 2 + 1][0], bfr[nip * 2 + 1][1], addr);
            }
#pragma unroll
            for (int mi = 0; mi < 4; mi++)
#pragma unroll
                for (int ni = 0; ni < 4; ni++)
                    asm volatile(
                        "mma.sync.aligned.m16n8k16.row.col.f32.bf16.bf16.f32 "
                        "{%0,%1,%2,%3}, {%4,%5,%6,%7}, {%8,%9}, {%0,%1,%2,%3};\n"
                        : "+f"(acc[mi][ni][0]), "+f"(acc[mi][ni][1]),
                          "+f"(acc[mi][ni][2]), "+f"(acc[mi][ni][3])
                        : "r"(af[mi][0]), "r"(af[mi][1]), "r"(af[mi][2]), "r"(af[mi][3]),
                          "r"(bfr[ni][0]), "r"(bfr[ni][1]));
        }
        buf = (buf == 2) ? 0 : buf + 1;
        buf2 = (buf2 == 2) ? 0 : buf2 + 1;
    }

#pragma unroll
    for (int mi = 0; mi < 4; mi++) {
#pragma unroll
        for (int ni = 0; ni < 4; ni++) {
            int r = bm + wm + mi * 16 + (lane >> 2);
            int cc = bn + wn + ni * 8 + (lane & 3) * 2;
            *(float2*)&g_C[(size_t)r * ldc + cc] = make_float2(acc[mi][ni][0], acc[mi][ni][1]);
            *(float2*)&g_C[(size_t)(r + 8) * ldc + cc] = make_float2(acc[mi][ni][2], acc[mi][ni][3]);
        }
    }
}

// ---------------- fused scale + LayerNorm + SiLU + re-quantize ----------------
__global__ void ln_silu_quant(const float* __restrict__ gamma, const float* __restrict__ beta,
                              int widx, double count) {
    int row = blockIdx.x;
    float wmean = fmaxf((float)(g_wsum[widx] / count), EPSV);
    float f = g_rs[row] * wmean;
    const float* cr = g_C + (size_t)row * HDIM;

    float v[16];
    float s = 0.0f;
#pragma unroll
    for (int i = 0; i < 16; i++) {
        v[i] = cr[threadIdx.x + i * 256] * f;
        s += v[i];
    }
    s = blockReduceSum(s);
    float mu = s * (1.0f / HDIM);

    float s2 = 0.0f;
#pragma unroll
    for (int i = 0; i < 16; i++) {
        float d = v[i] - mu;
        s2 += d * d;
    }
    s2 = blockReduceSum(s2);
    float inv_std = rsqrtf(s2 * (1.0f / HDIM) + EPSV);

    float y[16];
    float mx = 0.0f;
#pragma unroll
    for (int i = 0; i < 16; i++) {
        int j = threadIdx.x + i * 256;
        float t = (v[i] - mu) * inv_std * gamma[j] + beta[j];
        t = t / (1.0f + __expf(-t));  // silu
        y[i] = t;
        mx = fmaxf(mx, fabsf(t));
    }
    mx = blockReduceMax(mx);
    float scale = 127.0f / fmaxf(mx, EPSV);
#pragma unroll
    for (int i = 0; i < 16; i++) {
        int j = threadIdx.x + i * 256;
        float q = rintf(y[i] * scale);
        q = fminf(fmaxf(q, -128.0f), 127.0f);
        g_A[(size_t)row * HDIM + j] = __float2bfloat16(q);
    }
    if (threadIdx.x == 0) g_rs[row] = 1.0f / scale;
}

// ---------------- final sigmoid split ----------------
__global__ void final_kernel(float* __restrict__ out, double count) {
    int idx = blockIdx.x * blockDim.x + threadIdx.x;
    if (idx >= BATCH * 1000) return;
    int row = idx / 1000;
    int j = idx - row * 1000;
    float wmean = fmaxf((float)(g_wsum[3] / count), EPSV);
    float f = g_rs[row] * wmean;
    float l1 = g_C[(size_t)row * NOUT_PAD + j] * f;
    float l2 = g_C[(size_t)row * NOUT_PAD + 1000 + j] * f;
    float mz = 999.0f / (1.0f + __expf(-l1)) + 1.0f;
    float it = 100.0f / (1.0f + __expf(-l2));
    out[(size_t)row * 1000 + j] = mz;
    out[(size_t)BATCH * 1000 + (size_t)row * 1000 + j] = it;
}

// ---------------- launch ----------------
extern "C" void kernel_launch(void* const* d_in, const int* in_sizes, int n_in,
                              void* d_out, int out_size) {
    const float* x  = (const float*)d_in[0];
    const float* W0 = (const float*)d_in[1];
    const float* W1 = (const float*)d_in[2];
    const float* W2 = (const float*)d_in[3];
    const float* W3 = (const float*)d_in[4];
    const float* g0 = (const float*)d_in[5];
    const float* b0 = (const float*)d_in[6];
    const float* g1 = (const float*)d_in[7];
    const float* b1 = (const float*)d_in[8];
    const float* g2 = (const float*)d_in[9];
    const float* b2 = (const float*)d_in[10];
    float* out = (float*)d_out;

    cudaFuncSetAttribute(gemm_bf16, cudaFuncAttributeMaxDynamicSharedMemorySize, GEMM_SMEM);

    const double c0 = (double)HDIM * DIN;
    const double c1 = (double)HDIM * HDIM;
    const double c3 = (double)NOUT * HDIM;

    wsum_kernel<<<2048, 256>>>(W0, HDIM * DIN, 0);
    wsum_kernel<<<2048, 256>>>(W1, HDIM * HDIM, 1);
    wsum_kernel<<<2048, 256>>>(W2, HDIM * HDIM, 2);
    wsum_kernel<<<2048, 256>>>(W3, NOUT * HDIM, 3);
    wreduce_kernel<<<4, 256>>>();

    actquant_x<<<BATCH, 256>>>(x);

    // Layer 0: K=1024
    tern_kernel<<<2048, 256>>>(W0, HDIM, DIN, HDIM, 0, c0);
    gemm_bf16<<<dim3(HDIM / 128, BATCH / 128), 256, GEMM_SMEM>>>(DIN, HDIM);
    ln_silu_quant<<<BATCH, 256>>>(g0, b0, 0, c0);

    // Layer 1
    tern_kernel<<<2048, 256>>>(W1, HDIM, HDIM, HDIM, 1, c1);
    gemm_bf16<<<dim3(HDIM / 128, BATCH / 128), 256, GEMM_SMEM>>>(HDIM, HDIM);
    ln_silu_quant<<<BATCH, 256>>>(g1, b1, 1, c1);

    // Layer 2
    tern_kernel<<<2048, 256>>>(W2, HDIM, HDIM, HDIM, 2, c1);
    gemm_bf16<<<dim3(HDIM / 128, BATCH / 128), 256, GEMM_SMEM>>>(HDIM, HDIM);
    ln_silu_quant<<<BATCH, 256>>>(g2, b2, 2, c1);

    // Layer 3: output head, N padded 2000 -> 2048 with zero rows
    tern_kernel<<<2048, 256>>>(W3, NOUT, HDIM, NOUT_PAD, 3, c3);
    gemm_bf16<<<dim3(NOUT_PAD / 128, BATCH / 128), 256, GEMM_SMEM>>>(HDIM, NOUT_PAD);
    final_kernel<<<(BATCH * 1000 + 255) / 256, 256>>>(out, c3);
}